// round 11
// baseline (speedup 1.0000x reference)
#include <cuda_runtime.h>
#include <cuda_fp16.h>
#include <stdint.h>

#define Bb 256
#define Tt 512
#define Dd 128
#define Hh 512
#define Cc 10

#define NCTA 128        // 16 clusters x 8 CTAs
#define NTH  256
#define CLS  8          // cluster size = CTAs per batch tile
#define BM   16         // batch rows per CTA
#define HC   64         // h outputs per CTA

// ---- shared memory layout (bytes) ----
#define LDW 520                 // padded row stride in halves (512+8)
#define OFF_A0  0               // c tile buf 0: 16 x 520 halves = 16640 B
#define OFF_A1  16640           // c tile buf 1
#define OFF_W   33280           // weight stage: 64 x 520 halves = 66560 B (Wo parked)
#define OFF_TOK 99840           // uchar [512][16] tokens (8192 B)
#define OFF_CM  108032          // float [16][65] master c (4160 B)
#define LDCM 65
#define OFF_LUT 112192          // float [4][3][64] (3072 B)
#define OFF_BAR 115264          // 4 mbarriers x 8B: full0, full1, empty0, empty1
#define SMEM_TOTAL 115328

// ---- device globals ----
__device__ __half g_Wh[3][Hh*Hh];        // fp16 Wfh, Wih, Woh
__device__ float  g_h[Bb*Hh];            // final hidden state
__device__ float  g_lut[4*3*Hh];         // gate LUT; gate 3 (cs) pre-sigmoided
__device__ unsigned char g_xT[Tt*Bb];    // tokens transposed to [T][B]

// =============== setup kernel ===============
__global__ void setup_kernel(const int* __restrict__ x, const float* __restrict__ emb,
    const float* __restrict__ Wfx, const float* __restrict__ bf,
    const float* __restrict__ Wix, const float* __restrict__ bi,
    const float* __restrict__ Wox, const float* __restrict__ bo,
    const float* __restrict__ Wcx, const float* __restrict__ bc,
    const float* __restrict__ Wfh, const float* __restrict__ Wih,
    const float* __restrict__ Woh)
{
    int id = blockIdx.x*blockDim.x + threadIdx.x;
    int n  = gridDim.x*blockDim.x;
    for (int i = id; i < 4*3*Hh; i += n){
        int g = i/(3*Hh); int rem = i%(3*Hh); int v = rem/Hh; int h = rem%Hh;
        const float *W, *bb_;
        if      (g==0){ W=Wfx; bb_=bf; }
        else if (g==1){ W=Wix; bb_=bi; }
        else if (g==2){ W=Wox; bb_=bo; }
        else          { W=Wcx; bb_=bc; }
        float s = bb_[h];
        const float* e = emb + v*Dd;
        const float* w = W + (size_t)h*Dd;
        #pragma unroll 4
        for (int d = 0; d < Dd; d++) s += e[d]*w[d];
        if (g==3) s = 1.f/(1.f+expf(-s));
        g_lut[i] = s;
    }
    for (int i = id; i < Hh*Hh; i += n){
        g_Wh[0][i] = __float2half(Wfh[i]);
        g_Wh[1][i] = __float2half(Wih[i]);
        g_Wh[2][i] = __float2half(Woh[i]);
    }
    for (int i = id; i < Tt*Bb; i += n){
        int tt = i / Bb, bb2 = i % Bb;
        g_xT[i] = (unsigned char)x[bb2*Tt + tt];
    }
}

// =============== PTX helpers ===============
__device__ __forceinline__ void cpa16(uint32_t s, const void* g){
    asm volatile("cp.async.cg.shared.global [%0], [%1], 16;\n" :: "r"(s), "l"(g));
}
__device__ __forceinline__ void cpa_commit_wait(){
    asm volatile("cp.async.commit_group;\n");
    asm volatile("cp.async.wait_group 0;\n");
}
__device__ __forceinline__ void ldsm_x4(uint32_t &r0,uint32_t &r1,uint32_t &r2,uint32_t &r3, uint32_t a){
    asm volatile("ldmatrix.sync.aligned.m8n8.x4.shared.b16 {%0,%1,%2,%3}, [%4];\n"
        : "=r"(r0),"=r"(r1),"=r"(r2),"=r"(r3) : "r"(a));
}
__device__ __forceinline__ void ldsm_x2(uint32_t &r0,uint32_t &r1, uint32_t a){
    asm volatile("ldmatrix.sync.aligned.m8n8.x2.shared.b16 {%0,%1}, [%2];\n"
        : "=r"(r0),"=r"(r1) : "r"(a));
}
__device__ __forceinline__ void mma16816(float* c,
    uint32_t a0,uint32_t a1,uint32_t a2,uint32_t a3, uint32_t b0,uint32_t b1){
    asm volatile("mma.sync.aligned.m16n8k16.row.col.f32.f16.f16.f32 "
        "{%0,%1,%2,%3},{%4,%5,%6,%7},{%8,%9},{%0,%1,%2,%3};\n"
        : "+f"(c[0]),"+f"(c[1]),"+f"(c[2]),"+f"(c[3])
        : "r"(a0),"r"(a1),"r"(a2),"r"(a3),"r"(b0),"r"(b1));
}
__device__ __forceinline__ float sigm(float x){ return 1.f/(1.f+__expf(-x)); }

__device__ __forceinline__ void mbar_init(uint32_t a, uint32_t cnt){
    asm volatile("mbarrier.init.shared.b64 [%0], %1;" :: "r"(a), "r"(cnt) : "memory");
}
__device__ __forceinline__ void mbar_wait(uint32_t a, int ph){
    asm volatile(
        "{\n\t.reg .pred P;\n\t"
        "W_%=:\n\t"
        "mbarrier.try_wait.parity.acquire.cluster.shared::cta.b64 P, [%0], %1, 0x989680;\n\t"
        "@P bra D_%=;\n\t"
        "bra W_%=;\n\t"
        "D_%=:\n\t}\n"
        :: "r"(a), "r"(ph) : "memory");
}
__device__ __forceinline__ void arrive_remote(uint32_t localBar, int rank){
    uint32_t r;
    asm volatile("mapa.shared::cluster.u32 %0, %1, %2;" : "=r"(r) : "r"(localBar), "r"(rank));
    asm volatile("mbarrier.arrive.release.cluster.shared::cluster.b64 _, [%0];" :: "r"(r) : "memory");
}
__device__ __forceinline__ void st_remote32(uint32_t localAddr, int rank, uint32_t val){
    uint32_t r;
    asm volatile("mapa.shared::cluster.u32 %0, %1, %2;" : "=r"(r) : "r"(localAddr), "r"(rank));
    asm volatile("st.shared::cluster.u32 [%0], %1;" :: "r"(r), "r"(val) : "memory");
}
__device__ __forceinline__ void fence_cluster(){
    asm volatile("fence.acq_rel.cluster;" ::: "memory");
}
__device__ __forceinline__ void cluster_sync(){
    asm volatile("barrier.cluster.arrive.aligned;" ::: "memory");
    asm volatile("barrier.cluster.wait.aligned;" ::: "memory");
}

// =============== persistent LSTM kernel (clustered) ===============
__global__ void __launch_bounds__(NTH, 1) __cluster_dims__(CLS, 1, 1) lstm_kernel()
{
    extern __shared__ char smem[];
    uint32_t sbase = (uint32_t)__cvta_generic_to_shared(smem);
    int tid = threadIdx.x;
    int cta = blockIdx.x;
    int jt = cta & 7;            // h tile == cluster rank
    int mt = cta >> 3;           // batch tile (cluster id)
    int b0 = mt*BM, h0 = jt*HC;

    float* sCm = (float*)(smem + OFF_CM);
    float* sLut = (float*)(smem + OFF_LUT);
    unsigned char* sTok = (unsigned char*)(smem + OFF_TOK);

    uint32_t FULL0  = sbase + OFF_BAR + 0;
    uint32_t FULL1  = sbase + OFF_BAR + 8;
    uint32_t EMPTY0 = sbase + OFF_BAR + 16;
    uint32_t EMPTY1 = sbase + OFF_BAR + 24;

    // --- init barriers + zero A0 ---
    if (tid == 0){
        mbar_init(FULL0, CLS); mbar_init(FULL1, CLS);
        mbar_init(EMPTY0, CLS); mbar_init(EMPTY1, CLS);
    }
    for (int i = tid; i < 16640/4; i += NTH)
        *(uint32_t*)(smem + OFF_A0 + i*4) = 0u;

    int wid = tid >> 5, lane = tid & 31;
    int g4 = lane >> 2, t4 = lane & 3;

    // --- per-warp mma geometry ---
    uint32_t aAoff = (uint32_t)(((lane & 15)*LDW) + ((lane >> 4) & 1)*8)*2;
    uint32_t aA_0 = sbase + OFF_A0 + aAoff;
    uint32_t aA_1 = sbase + OFF_A1 + aAoff;
    int rowBn = wid*8 + (lane & 7);
    uint32_t colBn = ((lane >> 3) & 1) * 8;
    uint32_t aBW = sbase + OFF_W + (uint32_t)(rowBn*LDW + colBn)*2;

    // --- stage + hoist weights (once) ---
    uint32_t Bf[64], Bi[64];
    for (int i = tid; i < 64*64; i += NTH){
        int r = i >> 6, ck = i & 63;
        cpa16(sbase + OFF_W + (uint32_t)(r*LDW + ck*8)*2,
              &g_Wh[0][(size_t)(h0+r)*Hh + ck*8]);
    }
    cpa_commit_wait();
    __syncthreads();
    #pragma unroll
    for (int ks = 0; ks < 32; ks++)
        ldsm_x2(Bf[2*ks], Bf[2*ks+1], aBW + ks*32);
    __syncthreads();
    for (int i = tid; i < 64*64; i += NTH){
        int r = i >> 6, ck = i & 63;
        cpa16(sbase + OFF_W + (uint32_t)(r*LDW + ck*8)*2,
              &g_Wh[1][(size_t)(h0+r)*Hh + ck*8]);
    }
    cpa_commit_wait();
    __syncthreads();
    #pragma unroll
    for (int ks = 0; ks < 32; ks++)
        ldsm_x2(Bi[2*ks], Bi[2*ks+1], aBW + ks*32);
    __syncthreads();
    // Wo parked in OFF_W until t = Tt-1
    for (int i = tid; i < 64*64; i += NTH){
        int r = i >> 6, ck = i & 63;
        cpa16(sbase + OFF_W + (uint32_t)(r*LDW + ck*8)*2,
              &g_Wh[2][(size_t)(h0+r)*Hh + ck*8]);
    }
    for (int i = tid; i < 4*3*HC; i += NTH){
        int g = i/(3*HC), v = (i/HC)%3, h = i%HC;
        sLut[(g*3+v)*HC + h] = g_lut[(g*3+v)*Hh + h0 + h];
    }
    for (int i = tid; i < BM*LDCM; i += NTH) sCm[i] = 0.f;
    for (int i = tid; i < Tt*BM; i += NTH){
        int tt = i >> 4, bb2 = i & 15;
        sTok[i] = g_xT[tt*Bb + b0 + bb2];
    }
    cpa_commit_wait();
    __syncthreads();
    cluster_sync();     // barriers init'd + A0 zeroed in ALL cluster CTAs

    // elementwise cell ownership (matches mma accumulator layout)
    int r1 = g4, r2 = g4 + 8;
    int c0 = wid*8 + t4*2;
    // local store addresses for my c values in each buffer (col h0+c0 of full tile)
    uint32_t sA0r1 = sbase + OFF_A0 + (uint32_t)(r1*LDW + h0 + c0)*2;
    uint32_t sA0r2 = sbase + OFF_A0 + (uint32_t)(r2*LDW + h0 + c0)*2;
    uint32_t sA1r1 = sbase + OFF_A1 + (uint32_t)(r1*LDW + h0 + c0)*2;
    uint32_t sA1r2 = sbase + OFF_A1 + (uint32_t)(r2*LDW + h0 + c0)*2;

    for (int t = 0; t < Tt; t++){
        int buf = t & 1;
        int p = ((t-1) >> 1) & 1;
        uint32_t fullB   = buf ? FULL1  : FULL0;
        uint32_t fullBn  = buf ? FULL0  : FULL1;
        uint32_t emptyB  = buf ? EMPTY1 : EMPTY0;
        uint32_t emptyBn = buf ? EMPTY0 : EMPTY1;

        // --- wait for all 8 producers' c data in my A[buf] ---
        if (t > 0) mbar_wait(fullB, p);

        // --- GEMM from A[buf]; B in registers ---
        uint32_t aA = buf ? aA_1 : aA_0;
        float accF[4] = {0,0,0,0}, accI[4] = {0,0,0,0};
        #pragma unroll
        for (int ks = 0; ks < 32; ks++){
            uint32_t a0,a1,a2,a3;
            ldsm_x4(a0,a1,a2,a3, aA + ks*32);
            mma16816(accF, a0,a1,a2,a3, Bf[2*ks], Bf[2*ks+1]);
            mma16816(accI, a0,a1,a2,a3, Bi[2*ks], Bi[2*ks+1]);
        }
        __syncthreads();                       // all reads of A[buf] done
        if (tid < CLS) arrive_remote(emptyB, tid);   // free my A[buf] to producers

        // --- elementwise in registers ---
        int v1 = (int)sTok[(t << 4) + r1];
        int v2 = (int)sTok[(t << 4) + r2];
        const float* lutF1 = sLut + (0*3+v1)*HC;
        const float* lutI1 = sLut + (1*3+v1)*HC;
        const float* lutC1 = sLut + (3*3+v1)*HC;
        const float* lutF2 = sLut + (0*3+v2)*HC;
        const float* lutI2 = sLut + (1*3+v2)*HC;
        const float* lutC2 = sLut + (3*3+v2)*HC;

        float f00 = sigm(accF[0] + lutF1[c0]);
        float f01 = sigm(accF[1] + lutF1[c0+1]);
        float f10 = sigm(accF[2] + lutF2[c0]);
        float f11 = sigm(accF[3] + lutF2[c0+1]);
        float i00 = sigm(accI[0] + lutI1[c0]);
        float i01 = sigm(accI[1] + lutI1[c0+1]);
        float i10 = sigm(accI[2] + lutI2[c0]);
        float i11 = sigm(accI[3] + lutI2[c0+1]);

        float cn00 = lutC1[c0]  *i00 + sCm[r1*LDCM + c0]  *f00;
        float cn01 = lutC1[c0+1]*i01 + sCm[r1*LDCM + c0+1]*f01;
        float cn10 = lutC2[c0]  *i10 + sCm[r2*LDCM + c0]  *f10;
        float cn11 = lutC2[c0+1]*i11 + sCm[r2*LDCM + c0+1]*f11;
        sCm[r1*LDCM + c0]   = cn00;
        sCm[r1*LDCM + c0+1] = cn01;
        sCm[r2*LDCM + c0]   = cn10;
        sCm[r2*LDCM + c0+1] = cn11;

        if (t < Tt-1){
            // --- push fp16 c to all peers' A[buf^1] over DSMEM ---
            __half2 h2a = __halves2half2(__float2half(cn00), __float2half(cn01));
            __half2 h2b = __halves2half2(__float2half(cn10), __float2half(cn11));
            uint32_t va = *(uint32_t*)&h2a;
            uint32_t vb = *(uint32_t*)&h2b;
            uint32_t d1 = buf ? sA0r1 : sA1r1;
            uint32_t d2 = buf ? sA0r2 : sA1r2;
            if (t > 0) mbar_wait(emptyBn, p);   // peers freed their A[buf^1]
            #pragma unroll
            for (int pp = 0; pp < CLS; pp++){
                st_remote32(d1, pp, va);
                st_remote32(d2, pp, vb);
            }
            __syncthreads();                    // all threads' stores issued
            if (tid < CLS){
                fence_cluster();                // publish stores at cluster scope
                arrive_remote(fullBn, tid);     // signal peer tid: my slice arrived
            }
        } else {
            // o-gate matvec (once), Wo parked in SMEM
            float acco[4] = {0,0,0,0};
            #pragma unroll 8
            for (int ks = 0; ks < 32; ks++){
                uint32_t a0,a1,a2,a3,o0,o1;
                ldsm_x4(a0,a1,a2,a3, aA + ks*32);
                ldsm_x2(o0,o1, aBW + ks*32);
                mma16816(acco, a0,a1,a2,a3, o0,o1);
            }
            const float* lutO1 = sLut + (2*3+v1)*HC;
            const float* lutO2 = sLut + (2*3+v2)*HC;
            g_h[(size_t)(b0+r1)*Hh + h0 + c0]   = tanhf(cn00)*sigm(acco[0] + lutO1[c0]);
            g_h[(size_t)(b0+r1)*Hh + h0 + c0+1] = tanhf(cn01)*sigm(acco[1] + lutO1[c0+1]);
            g_h[(size_t)(b0+r2)*Hh + h0 + c0]   = tanhf(cn10)*sigm(acco[2] + lutO2[c0]);
            g_h[(size_t)(b0+r2)*Hh + h0 + c0+1] = tanhf(cn11)*sigm(acco[3] + lutO2[c0+1]);
        }
    }
    cluster_sync();     // no CTA exits while peers may still touch its SMEM
}

// =============== classifier + log_softmax ===============
__global__ void cls_kernel(const float* __restrict__ Wph, const float* __restrict__ bp,
                           float* __restrict__ out)
{
    int b = blockIdx.x, lane = threadIdx.x;
    const float* hr = g_h + (size_t)b*Hh;
    float p[Cc];
    #pragma unroll
    for (int c = 0; c < Cc; c++){
        float s = 0.f;
        for (int k = lane; k < Hh; k += 32) s += hr[k]*Wph[c*Hh + k];
        #pragma unroll
        for (int o = 16; o; o >>= 1) s += __shfl_xor_sync(0xffffffffu, s, o);
        p[c] = s + bp[c];
    }
    float mx = p[0];
    #pragma unroll
    for (int c = 1; c < Cc; c++) mx = fmaxf(mx, p[c]);
    float se = 0.f;
    #pragma unroll
    for (int c = 0; c < Cc; c++) se += expf(p[c]-mx);
    float lse = mx + logf(se);
    if (lane < Cc) out[b*Cc + lane] = p[lane] - lse;
}

// =============== launch ===============
extern "C" void kernel_launch(void* const* d_in, const int* in_sizes, int n_in,
                              void* d_out, int out_size)
{
    const int*   x   = (const int*)  d_in[0];
    const float* emb = (const float*)d_in[1];
    const float* Wfx = (const float*)d_in[2];
    const float* Wfh = (const float*)d_in[3];
    const float* bf  = (const float*)d_in[4];
    const float* Wix = (const float*)d_in[5];
    const float* Wih = (const float*)d_in[6];
    const float* bi  = (const float*)d_in[7];
    const float* Wox = (const float*)d_in[8];
    const float* Woh = (const float*)d_in[9];
    const float* bo  = (const float*)d_in[10];
    const float* Wcx = (const float*)d_in[11];
    const float* bc  = (const float*)d_in[12];
    const float* Wph = (const float*)d_in[13];
    const float* bp  = (const float*)d_in[14];
    float* out = (float*)d_out;

    cudaFuncSetAttribute(lstm_kernel,
        cudaFuncAttributeMaxDynamicSharedMemorySize, SMEM_TOTAL);

    setup_kernel<<<256,256>>>(x, emb, Wfx, bf, Wix, bi, Wox, bo, Wcx, bc,
                              Wfh, Wih, Woh);
    lstm_kernel<<<NCTA, NTH, SMEM_TOTAL>>>();
    cls_kernel<<<Bb, 32>>>(Wph, bp, out);
}